// round 4
// baseline (speedup 1.0000x reference)
#include <cuda_runtime.h>
#include <math.h>

// ROI max pooling (matches JAX reference bit-exactly for this input distribution).
//
// Pass 1: transpose feat [2,256,38,38] (NCHW) -> featT [2,38,38,256] (NHWC)
//         into __device__ scratch. 3 MB, tiled smem transpose, fully coalesced.
// Pass 2: block = (roi, channel-chunk of 64). All 49 bin bounds are
//         block-uniform (smem) -> zero warp divergence. Warp lanes = 32
//         consecutive channels -> every feature load is a coalesced 128B
//         transaction. Results staged in smem, then written linearly
//         (coalesced) to the output region.
//
// Bounds math (all non-negative, replicates Python floor-div exactly):
//   x1 = floor(roi_x1/16) ... rh = y2-y1+1, rw = x2-x1+1
//   hstart_i = y1 + (i*rh)/7,  hend_i = y1 + ((i+1)*rh + 6)/7
// Given coords in [0, 607.9], windows always lie in [0,38) and are non-empty.

#define N_IMG 2
#define CHN   256
#define H_    38
#define W_    38
#define HW    (H_ * W_)          // 1444
#define NUM_ROIS 256
#define OUT_H 7
#define OUT_W 7
#define BINS  (OUT_H * OUT_W)    // 49
#define SPATIAL_SCALE 0.0625f

#define TC 64                    // channels (threads) per block in main kernel

// channels-last scratch: [N][H][W][C]
__device__ float g_featT[N_IMG * HW * CHN];

// ---------------------------------------------------------------------------
// Pass 1: NCHW -> NHWC transpose. Per image: [C=256][HW=1444] -> [HW][C].
// Tiled 32x32 through smem, coalesced reads and writes.
// ---------------------------------------------------------------------------
__global__ void transpose_kernel(const float* __restrict__ in)
{
    __shared__ float tile[32][33];
    int n   = blockIdx.z;
    int hw0 = blockIdx.x * 32;   // position dim (fast in input)
    int c0  = blockIdx.y * 32;   // channel dim

    const float* inp  = in      + (size_t)n * CHN * HW;
    float*       outp = g_featT + (size_t)n * HW * CHN;

    // read: in[n][c0+y+k][hw0+x]  (coalesced along hw)
    #pragma unroll
    for (int k = 0; k < 32; k += 8) {
        int c  = c0 + threadIdx.y + k;
        int hw = hw0 + threadIdx.x;
        tile[threadIdx.y + k][threadIdx.x] =
            (hw < HW) ? inp[(size_t)c * HW + hw] : 0.0f;
    }
    __syncthreads();
    // write: out[n][hw0+y+k][c0+x]  (coalesced along c)
    #pragma unroll
    for (int k = 0; k < 32; k += 8) {
        int hw = hw0 + threadIdx.y + k;
        if (hw < HW)
            outp[(size_t)hw * CHN + c0 + threadIdx.x] =
                tile[threadIdx.x][threadIdx.y + k];
    }
}

// ---------------------------------------------------------------------------
// Pass 2: ROI pooling on channels-last layout.
// grid = (NUM_ROIS, CHN/TC), block = TC threads (one channel each).
// ---------------------------------------------------------------------------
__global__ void __launch_bounds__(TC)
roi_pool_nhwc(const float* __restrict__ rois, float* __restrict__ out)
{
    __shared__ int   s_hs[OUT_H], s_he[OUT_H], s_ws[OUT_W], s_we[OUT_W];
    __shared__ int   s_b;
    __shared__ float stage[TC * BINS];

    int roi = blockIdx.x;
    int c   = blockIdx.y * TC + threadIdx.x;

    if (threadIdx.x == 0) {
        const float* r = rois + roi * 5;
        int b  = (int)r[0];
        int x1 = (int)floorf(r[1] * SPATIAL_SCALE);
        int y1 = (int)floorf(r[2] * SPATIAL_SCALE);
        int x2 = (int)floorf(r[3] * SPATIAL_SCALE);
        int y2 = (int)floorf(r[4] * SPATIAL_SCALE);
        int rh = y2 - y1 + 1;
        int rw = x2 - x1 + 1;
        s_b = b;
        #pragma unroll
        for (int i = 0; i < OUT_H; ++i) {
            s_hs[i] = y1 + (i * rh) / OUT_H;
            s_he[i] = y1 + ((i + 1) * rh + OUT_H - 1) / OUT_H;
        }
        #pragma unroll
        for (int j = 0; j < OUT_W; ++j) {
            s_ws[j] = x1 + (j * rw) / OUT_W;
            s_we[j] = x1 + ((j + 1) * rw + OUT_W - 1) / OUT_W;
        }
    }
    __syncthreads();

    // copy w-bounds to registers (static indexing via unrolled loops)
    int lws[OUT_W], lwe[OUT_W];
    #pragma unroll
    for (int j = 0; j < OUT_W; ++j) { lws[j] = s_ws[j]; lwe[j] = s_we[j]; }

    const float* base = g_featT + (size_t)s_b * HW * CHN + c;
    const float NEG_INF = -__int_as_float(0x7f800000);

    for (int i = 0; i < OUT_H; ++i) {
        float m[OUT_W];
        #pragma unroll
        for (int j = 0; j < OUT_W; ++j) m[j] = NEG_INF;

        int hend = s_he[i];
        for (int h = s_hs[i]; h < hend; ++h) {
            const float* rp = base + (size_t)(h * W_) * CHN;
            #pragma unroll
            for (int j = 0; j < OUT_W; ++j) {
                for (int w = lws[j]; w < lwe[j]; ++w) {
                    m[j] = fmaxf(m[j], rp[(size_t)w * CHN]);
                }
            }
        }
        #pragma unroll
        for (int j = 0; j < OUT_W; ++j)
            stage[threadIdx.x * BINS + i * OUT_W + j] = m[j];
    }
    __syncthreads();

    // coalesced linear write of this block's output region
    float* obase = out + ((size_t)roi * CHN + (size_t)blockIdx.y * TC) * BINS;
    #pragma unroll 7
    for (int t = threadIdx.x; t < TC * BINS; t += TC)
        obase[t] = stage[t];
}

extern "C" void kernel_launch(void* const* d_in, const int* in_sizes, int n_in,
                              void* d_out, int out_size)
{
    const float* feat = (const float*)d_in[0];
    const float* rois = (const float*)d_in[1];
    float* out = (float*)d_out;

    // Pass 1: transpose to NHWC scratch
    dim3 tgrid((HW + 31) / 32, CHN / 32, N_IMG);   // (46, 8, 2)
    dim3 tblock(32, 8);
    transpose_kernel<<<tgrid, tblock>>>(feat);

    // Pass 2: ROI pooling
    dim3 pgrid(NUM_ROIS, CHN / TC);                // (256, 4)
    roi_pool_nhwc<<<pgrid, TC>>>(rois, out);
}

// round 5
// speedup vs baseline: 4.6829x; 4.6829x over previous
#include <cuda_runtime.h>
#include <math.h>

// ROI max pooling, two-pass:
//   Pass 1: NCHW [2,256,38,38] -> NHWC scratch [2,38,38,256] (tiled smem transpose).
//   Pass 2: block = (roi, i-row of the 7x7 grid), 256 threads = 256 channels.
//           All loop bounds block-uniform -> zero divergence. Warp lanes =
//           32 consecutive channels -> every feature load is one fully-used
//           128B transaction. 7 independent bin accumulators per thread.
//
// Bin math (non-negative ints, replicates Python floor-div exactly):
//   x1=floor(rx1/16), ... , rh=y2-y1+1, rw=x2-x1+1
//   hstart_i = y1 + (i*rh)/7, hend_i = y1 + ((i+1)*rh+6)/7   (same for w/j)
// Coords in [0,607.9] => windows lie inside [0,38), always non-empty.

#define N_IMG 2
#define CHN   256
#define H_    38
#define W_    38
#define HW    (H_ * W_)          // 1444
#define NUM_ROIS 256
#define OUT_H 7
#define OUT_W 7
#define BINS  (OUT_H * OUT_W)
#define SPATIAL_SCALE 0.0625f

// channels-last scratch: [N][H][W][C]
__device__ float g_featT[N_IMG * HW * CHN];

// ---------------------------------------------------------------------------
// Pass 1: NCHW -> NHWC transpose (32x32 tiles through smem).
// ---------------------------------------------------------------------------
__global__ void transpose_kernel(const float* __restrict__ in)
{
    __shared__ float tile[32][33];
    int n   = blockIdx.z;
    int hw0 = blockIdx.x * 32;
    int c0  = blockIdx.y * 32;

    const float* inp  = in      + (size_t)n * CHN * HW;
    float*       outp = g_featT + (size_t)n * HW * CHN;

    #pragma unroll
    for (int k = 0; k < 32; k += 8) {
        int c  = c0 + threadIdx.y + k;
        int hw = hw0 + threadIdx.x;
        tile[threadIdx.y + k][threadIdx.x] =
            (hw < HW) ? inp[(size_t)c * HW + hw] : 0.0f;
    }
    __syncthreads();
    #pragma unroll
    for (int k = 0; k < 32; k += 8) {
        int hw = hw0 + threadIdx.y + k;
        if (hw < HW)
            outp[(size_t)hw * CHN + c0 + threadIdx.x] =
                tile[threadIdx.x][threadIdx.y + k];
    }
}

// ---------------------------------------------------------------------------
// Pass 2: grid = (NUM_ROIS, OUT_H), block = 256 threads (one channel each).
// Each thread produces out[roi][c][i][0..6].
// ---------------------------------------------------------------------------
__global__ void __launch_bounds__(CHN)
roi_pool_rows(const float* __restrict__ rois, float* __restrict__ out)
{
    int roi = blockIdx.x;
    int i   = blockIdx.y;
    int c   = threadIdx.x;

    // Uniform per-block bounds; every thread computes them (broadcast L1 hits,
    // no smem/sync needed).
    const float* r = rois + roi * 5;
    int b  = (int)__ldg(r + 0);
    int x1 = (int)floorf(__ldg(r + 1) * SPATIAL_SCALE);
    int y1 = (int)floorf(__ldg(r + 2) * SPATIAL_SCALE);
    int x2 = (int)floorf(__ldg(r + 3) * SPATIAL_SCALE);
    int y2 = (int)floorf(__ldg(r + 4) * SPATIAL_SCALE);
    int rh = y2 - y1 + 1;
    int rw = x2 - x1 + 1;

    int hstart = y1 + (i * rh) / OUT_H;
    int hend   = y1 + ((i + 1) * rh + OUT_H - 1) / OUT_H;

    int ws[OUT_W], we[OUT_W];
    #pragma unroll
    for (int j = 0; j < OUT_W; ++j) {
        ws[j] = x1 + (j * rw) / OUT_W;
        we[j] = x1 + ((j + 1) * rw + OUT_W - 1) / OUT_W;
    }

    const float* base = g_featT + (size_t)b * HW * CHN + c;
    const float NEG_INF = -__int_as_float(0x7f800000);

    float m[OUT_W];
    #pragma unroll
    for (int j = 0; j < OUT_W; ++j) m[j] = NEG_INF;

    for (int h = hstart; h < hend; ++h) {
        const float* rp = base + (size_t)(h * W_) * CHN;
        #pragma unroll
        for (int j = 0; j < OUT_W; ++j) {
            const float* p = rp + (size_t)ws[j] * CHN;
            for (int w = ws[j]; w < we[j]; ++w) {
                m[j] = fmaxf(m[j], __ldg(p));
                p += CHN;
            }
        }
    }

    float* o = out + ((size_t)roi * CHN + c) * BINS + i * OUT_W;
    #pragma unroll
    for (int j = 0; j < OUT_W; ++j) o[j] = m[j];
}

extern "C" void kernel_launch(void* const* d_in, const int* in_sizes, int n_in,
                              void* d_out, int out_size)
{
    const float* feat = (const float*)d_in[0];
    const float* rois = (const float*)d_in[1];
    float* out = (float*)d_out;

    dim3 tgrid((HW + 31) / 32, CHN / 32, N_IMG);   // (46, 8, 2)
    dim3 tblock(32, 8);
    transpose_kernel<<<tgrid, tblock>>>(feat);

    dim3 pgrid(NUM_ROIS, OUT_H);                   // (256, 7)
    roi_pool_rows<<<pgrid, CHN>>>(rois, out);
}

// round 6
// speedup vs baseline: 4.6950x; 1.0026x over previous
#include <cuda_runtime.h>
#include <math.h>

// ROI max pooling, two-pass:
//   Pass 1: NCHW [2,256,38,38] -> NHWC scratch [2,38,38,256].
//   Pass 2: grid=(roi, i), block = 64 c4-lanes x 2 h-strips.
//           Thread = 4 consecutive channels (float4 loads -> 4x fewer
//           transactions, same fully-used bytes). All bounds block-uniform
//           (zero divergence). 7 independent float4 accumulators; the two
//           h-strips merge through smem.
//
// Bin math (non-negative ints == Python floor-div):
//   x1=floor(rx1/16),..., rh=y2-y1+1, rw=x2-x1+1
//   hstart_i = y1 + (i*rh)/7, hend_i = y1 + ((i+1)*rh+6)/7  (same for w/j)
// Coords in [0,607.9] => windows inside [0,38), non-empty.

#define N_IMG 2
#define CHN   256
#define C4    (CHN/4)            // 64 float4 lanes
#define H_    38
#define W_    38
#define HW    (H_ * W_)
#define NUM_ROIS 256
#define OUT_H 7
#define OUT_W 7
#define BINS  (OUT_H * OUT_W)
#define SPATIAL_SCALE 0.0625f
#define YS    2                  // h-strips per block

__device__ float g_featT[N_IMG * HW * CHN];   // [N][H][W][C]

__global__ void transpose_kernel(const float* __restrict__ in)
{
    __shared__ float tile[32][33];
    int n   = blockIdx.z;
    int hw0 = blockIdx.x * 32;
    int c0  = blockIdx.y * 32;

    const float* inp  = in      + (size_t)n * CHN * HW;
    float*       outp = g_featT + (size_t)n * HW * CHN;

    #pragma unroll
    for (int k = 0; k < 32; k += 8) {
        int c  = c0 + threadIdx.y + k;
        int hw = hw0 + threadIdx.x;
        tile[threadIdx.y + k][threadIdx.x] =
            (hw < HW) ? inp[(size_t)c * HW + hw] : 0.0f;
    }
    __syncthreads();
    #pragma unroll
    for (int k = 0; k < 32; k += 8) {
        int hw = hw0 + threadIdx.y + k;
        if (hw < HW)
            outp[(size_t)hw * CHN + c0 + threadIdx.x] =
                tile[threadIdx.x][threadIdx.y + k];
    }
}

__device__ __forceinline__ float4 max4(float4 a, float4 b)
{
    return make_float4(fmaxf(a.x, b.x), fmaxf(a.y, b.y),
                       fmaxf(a.z, b.z), fmaxf(a.w, b.w));
}

// grid = (NUM_ROIS, OUT_H), block = (C4, YS) = (64, 2)
__global__ void __launch_bounds__(C4 * YS)
roi_pool_v4(const float* __restrict__ rois, float* __restrict__ out)
{
    __shared__ float4 s_part[OUT_W * C4];   // strip-1 partials, [j][lane]

    int roi   = blockIdx.x;
    int i     = blockIdx.y;
    int lane  = threadIdx.x;   // c4 index
    int strip = threadIdx.y;

    const float* r = rois + roi * 5;
    int b  = (int)__ldg(r + 0);
    int x1 = (int)floorf(__ldg(r + 1) * SPATIAL_SCALE);
    int y1 = (int)floorf(__ldg(r + 2) * SPATIAL_SCALE);
    int x2 = (int)floorf(__ldg(r + 3) * SPATIAL_SCALE);
    int y2 = (int)floorf(__ldg(r + 4) * SPATIAL_SCALE);
    int rh = y2 - y1 + 1;
    int rw = x2 - x1 + 1;

    int hstart = y1 + (i * rh) / OUT_H;
    int hend   = y1 + ((i + 1) * rh + OUT_H - 1) / OUT_H;

    int ws[OUT_W], we[OUT_W];
    #pragma unroll
    for (int j = 0; j < OUT_W; ++j) {
        ws[j] = x1 + (j * rw) / OUT_W;
        we[j] = x1 + ((j + 1) * rw + OUT_W - 1) / OUT_W;
    }

    const float4* base = (const float4*)(g_featT + (size_t)b * HW * CHN) + lane;
    const float NI = -__int_as_float(0x7f800000);

    float4 m[OUT_W];
    #pragma unroll
    for (int j = 0; j < OUT_W; ++j) m[j] = make_float4(NI, NI, NI, NI);

    for (int h = hstart + strip; h < hend; h += YS) {
        const float4* rp = base + (size_t)(h * W_) * C4;
        #pragma unroll
        for (int j = 0; j < OUT_W; ++j) {
            const float4* p = rp + (size_t)ws[j] * C4;
            for (int w = ws[j]; w < we[j]; ++w) {
                m[j] = max4(m[j], *p);
                p += C4;
            }
        }
    }

    if (strip == 1) {
        #pragma unroll
        for (int j = 0; j < OUT_W; ++j)
            s_part[j * C4 + lane] = m[j];
    }
    __syncthreads();

    if (strip == 0) {
        #pragma unroll
        for (int j = 0; j < OUT_W; ++j)
            m[j] = max4(m[j], s_part[j * C4 + lane]);

        // out[roi][c][i*7 + j], c = lane*4 .. lane*4+3
        float* o = out + ((size_t)roi * CHN + (size_t)lane * 4) * BINS + i * OUT_W;
        #pragma unroll
        for (int j = 0; j < OUT_W; ++j) {
            o[j]            = m[j].x;
            o[BINS + j]     = m[j].y;
            o[2 * BINS + j] = m[j].z;
            o[3 * BINS + j] = m[j].w;
        }
    }
}

extern "C" void kernel_launch(void* const* d_in, const int* in_sizes, int n_in,
                              void* d_out, int out_size)
{
    const float* feat = (const float*)d_in[0];
    const float* rois = (const float*)d_in[1];
    float* out = (float*)d_out;

    dim3 tgrid((HW + 31) / 32, CHN / 32, N_IMG);
    dim3 tblock(32, 8);
    transpose_kernel<<<tgrid, tblock>>>(feat);

    dim3 pgrid(NUM_ROIS, OUT_H);
    dim3 pblock(C4, YS);
    roi_pool_v4<<<pgrid, pblock>>>(rois, out);
}

// round 7
// speedup vs baseline: 8.2553x; 1.7583x over previous
#include <cuda_runtime.h>
#include <math.h>

// ROI max pooling, two-pass:
//   Pass 1: NCHW [2,256,38,38] -> NHWC scratch [2,38,38,256].
//   Pass 2: grid = (roi, i).  block = (64 c4-lanes, 7 j-bins) = 448 threads.
//           Each thread: ONE bin (i,j) x 4 channels, one float4 accumulator,
//           ~8 independent float4 loads. j is warp-uniform -> zero divergence.
//           Output tile staged in smem, written back with coalesced runs.
//
// Bin math (non-negative ints == Python floor-div):
//   x1=floor(rx1/16),..., rh=y2-y1+1, rw=x2-x1+1
//   hstart_i = y1 + (i*rh)/7, hend_i = y1 + ((i+1)*rh+6)/7  (same for w/j)
// Coords in [0,607.9] => windows inside [0,38), non-empty.

#define N_IMG 2
#define CHN   256
#define C4    (CHN/4)            // 64
#define H_    38
#define W_    38
#define HW    (H_ * W_)
#define NUM_ROIS 256
#define OUT_H 7
#define OUT_W 7
#define BINS  (OUT_H * OUT_W)
#define SPATIAL_SCALE 0.0625f
#define PTHREADS (C4 * OUT_W)    // 448

__device__ float g_featT[N_IMG * HW * CHN];   // [N][H][W][C]

// ---------------------------------------------------------------------------
__global__ void transpose_kernel(const float* __restrict__ in)
{
    __shared__ float tile[32][33];
    int n   = blockIdx.z;
    int hw0 = blockIdx.x * 32;
    int c0  = blockIdx.y * 32;

    const float* inp  = in      + (size_t)n * CHN * HW;
    float*       outp = g_featT + (size_t)n * HW * CHN;

    #pragma unroll
    for (int k = 0; k < 32; k += 8) {
        int c  = c0 + threadIdx.y + k;
        int hw = hw0 + threadIdx.x;
        tile[threadIdx.y + k][threadIdx.x] =
            (hw < HW) ? inp[(size_t)c * HW + hw] : 0.0f;
    }
    __syncthreads();
    #pragma unroll
    for (int k = 0; k < 32; k += 8) {
        int hw = hw0 + threadIdx.y + k;
        if (hw < HW)
            outp[(size_t)hw * CHN + c0 + threadIdx.x] =
                tile[threadIdx.x][threadIdx.y + k];
    }
}

__device__ __forceinline__ float4 max4(float4 a, float4 b)
{
    return make_float4(fmaxf(a.x, b.x), fmaxf(a.y, b.y),
                       fmaxf(a.z, b.z), fmaxf(a.w, b.w));
}

// ---------------------------------------------------------------------------
// grid = (NUM_ROIS, OUT_H), block = (C4, OUT_W) = (64, 7)
__global__ void __launch_bounds__(PTHREADS, 4)
roi_pool_bin(const float* __restrict__ rois, float* __restrict__ out)
{
    __shared__ float4 s_out[OUT_W][C4];   // [j][c4]  (channels c4*4..c4*4+3)

    int roi  = blockIdx.x;
    int i    = blockIdx.y;
    int lane = threadIdx.x;               // c4 index
    int j    = threadIdx.y;               // warp-uniform

    const float* r = rois + roi * 5;
    int b  = (int)__ldg(r + 0);
    int x1 = (int)floorf(__ldg(r + 1) * SPATIAL_SCALE);
    int y1 = (int)floorf(__ldg(r + 2) * SPATIAL_SCALE);
    int x2 = (int)floorf(__ldg(r + 3) * SPATIAL_SCALE);
    int y2 = (int)floorf(__ldg(r + 4) * SPATIAL_SCALE);
    int rh = y2 - y1 + 1;
    int rw = x2 - x1 + 1;

    int hstart = y1 + (i * rh) / OUT_H;
    int hend   = y1 + ((i + 1) * rh + OUT_H - 1) / OUT_H;
    int wstart = x1 + (j * rw) / OUT_W;
    int wend   = x1 + ((j + 1) * rw + OUT_W - 1) / OUT_W;

    const float4* base = (const float4*)(g_featT + (size_t)b * HW * CHN) + lane;
    const float NI = -__int_as_float(0x7f800000);
    float4 m = make_float4(NI, NI, NI, NI);

    for (int h = hstart; h < hend; ++h) {
        const float4* p = base + (size_t)(h * W_ + wstart) * C4;
        for (int w = wstart; w < wend; ++w) {
            m = max4(m, *p);
            p += C4;
        }
    }

    s_out[j][lane] = m;        // consecutive lanes -> conflict-free 16B stores
    __syncthreads();

    // Write out[roi][c][i*7+j] for all c,j: 1792 floats, runs of 7 contiguous.
    const float* s = (const float*)s_out;  // s[j*256 + c]
    float* obase = out + (size_t)roi * CHN * BINS + i * OUT_W;
    int tid = threadIdx.y * C4 + threadIdx.x;
    #pragma unroll
    for (int t = tid; t < CHN * OUT_W; t += PTHREADS) {
        int c  = t / OUT_W;
        int jj = t % OUT_W;
        obase[(size_t)c * BINS + jj] = s[jj * CHN + c];
    }
}

extern "C" void kernel_launch(void* const* d_in, const int* in_sizes, int n_in,
                              void* d_out, int out_size)
{
    const float* feat = (const float*)d_in[0];
    const float* rois = (const float*)d_in[1];
    float* out = (float*)d_out;

    dim3 tgrid((HW + 31) / 32, CHN / 32, N_IMG);
    dim3 tblock(32, 8);
    transpose_kernel<<<tgrid, tblock>>>(feat);

    dim3 pgrid(NUM_ROIS, OUT_H);
    dim3 pblock(C4, OUT_W);
    roi_pool_bin<<<pgrid, pblock>>>(rois, out);
}

// round 8
// speedup vs baseline: 8.3435x; 1.0107x over previous
#include <cuda_runtime.h>
#include <math.h>

// ROI max pooling, two-pass:
//   Pass 1: NCHW [2,256,38,38] -> NHWC scratch [2,38,38,256]; block (0,0,0)
//           additionally precomputes all per-roi bin bounds (256 rois, one
//           thread each) into packed __device__ arrays.
//   Pass 2: grid = (roi, i). block = (64 c4-lanes, 7 j) = 448 threads.
//           Thread = one bin x 4 channels, one float4 accumulator pair,
//           bounds read as 3 packed ints (no per-thread divides).
//
// Bin math (non-negative ints == Python floor-div):
//   x1=floor(rx1/16),..., rh=y2-y1+1, rw=x2-x1+1
//   hstart_i = y1 + (i*rh)/7, hend_i = y1 + ((i+1)*rh+6)/7  (same for w/j)
// Coords in [0,607.9] => windows inside [0,38), non-empty.

#define N_IMG 2
#define CHN   256
#define C4    (CHN/4)            // 64
#define H_    38
#define W_    38
#define HW    (H_ * W_)
#define NUM_ROIS 256
#define OUT_H 7
#define OUT_W 7
#define BINS  (OUT_H * OUT_W)
#define SPATIAL_SCALE 0.0625f
#define PTHREADS (C4 * OUT_W)    // 448

__device__ float g_featT[N_IMG * HW * CHN];     // [N][H][W][C]
__device__ int   g_base4[NUM_ROIS];             // b * HW * C4 (float4 units)
__device__ int   g_hb[NUM_ROIS * OUT_H];        // hstart | hend<<8
__device__ int   g_wb[NUM_ROIS * OUT_W];        // wstart | wend<<8

// ---------------------------------------------------------------------------
// Pass 1: transpose + (block 0 only) per-roi bound precompute.
// ---------------------------------------------------------------------------
__global__ void transpose_kernel(const float* __restrict__ in,
                                 const float* __restrict__ rois)
{
    __shared__ float tile[32][33];
    int n   = blockIdx.z;
    int hw0 = blockIdx.x * 32;
    int c0  = blockIdx.y * 32;

    if (blockIdx.x == 0 && blockIdx.y == 0 && blockIdx.z == 0) {
        int t = threadIdx.y * 32 + threadIdx.x;     // 0..255
        if (t < NUM_ROIS) {
            const float* r = rois + t * 5;
            int b  = (int)r[0];
            int x1 = (int)floorf(r[1] * SPATIAL_SCALE);
            int y1 = (int)floorf(r[2] * SPATIAL_SCALE);
            int x2 = (int)floorf(r[3] * SPATIAL_SCALE);
            int y2 = (int)floorf(r[4] * SPATIAL_SCALE);
            int rh = y2 - y1 + 1;
            int rw = x2 - x1 + 1;
            g_base4[t] = b * HW * C4;
            #pragma unroll
            for (int i = 0; i < OUT_H; ++i) {
                int hs = y1 + (i * rh) / OUT_H;
                int he = y1 + ((i + 1) * rh + OUT_H - 1) / OUT_H;
                g_hb[t * OUT_H + i] = hs | (he << 8);
            }
            #pragma unroll
            for (int j = 0; j < OUT_W; ++j) {
                int ws = x1 + (j * rw) / OUT_W;
                int we = x1 + ((j + 1) * rw + OUT_W - 1) / OUT_W;
                g_wb[t * OUT_W + j] = ws | (we << 8);
            }
        }
    }

    const float* inp  = in      + (size_t)n * CHN * HW;
    float*       outp = g_featT + (size_t)n * HW * CHN;

    #pragma unroll
    for (int k = 0; k < 32; k += 8) {
        int c  = c0 + threadIdx.y + k;
        int hw = hw0 + threadIdx.x;
        tile[threadIdx.y + k][threadIdx.x] =
            (hw < HW) ? inp[(size_t)c * HW + hw] : 0.0f;
    }
    __syncthreads();
    #pragma unroll
    for (int k = 0; k < 32; k += 8) {
        int hw = hw0 + threadIdx.y + k;
        if (hw < HW)
            outp[(size_t)hw * CHN + c0 + threadIdx.x] =
                tile[threadIdx.x][threadIdx.y + k];
    }
}

__device__ __forceinline__ float4 max4(float4 a, float4 b)
{
    return make_float4(fmaxf(a.x, b.x), fmaxf(a.y, b.y),
                       fmaxf(a.z, b.z), fmaxf(a.w, b.w));
}

// ---------------------------------------------------------------------------
// Pass 2: grid = (NUM_ROIS, OUT_H), block = (C4, OUT_W) = (64, 7)
// ---------------------------------------------------------------------------
__global__ void __launch_bounds__(PTHREADS, 4)
roi_pool_bin(float* __restrict__ out)
{
    __shared__ float s[CHN * OUT_W];      // s[c*7 + j]

    int roi  = blockIdx.x;
    int i    = blockIdx.y;
    int lane = threadIdx.x;               // c4 index
    int j    = threadIdx.y;               // warp-uniform

    int hb = g_hb[roi * OUT_H + i];
    int wb = g_wb[roi * OUT_W + j];
    int hstart = hb & 0xff, hend = hb >> 8;
    int wstart = wb & 0xff, wend = wb >> 8;

    const float4* base = (const float4*)g_featT + g_base4[roi] + lane;
    const float NI = -__int_as_float(0x7f800000);
    float4 m0 = make_float4(NI, NI, NI, NI);
    float4 m1 = m0;

    int nw = wend - wstart;
    for (int h = hstart; h < hend; ++h) {
        const float4* p = base + (size_t)(h * W_ + wstart) * C4;
        int w = nw;
        while (w >= 2) {
            m0 = max4(m0, p[0]);
            m1 = max4(m1, p[C4]);
            p += 2 * C4;
            w -= 2;
        }
        if (w) m0 = max4(m0, p[0]);
    }
    float4 m = max4(m0, m1);

    // stage as s[c*7 + j]: 4 scalar stores (4-way bank conflict, cheap)
    int c0 = lane * 4;
    s[(c0 + 0) * OUT_W + j] = m.x;
    s[(c0 + 1) * OUT_W + j] = m.y;
    s[(c0 + 2) * OUT_W + j] = m.z;
    s[(c0 + 3) * OUT_W + j] = m.w;
    __syncthreads();

    // out[roi][c][i*7 + jj]; linear smem read, one div-by-7 per thread
    int tid = threadIdx.y * C4 + threadIdx.x;     // 0..447
    int cq  = tid / OUT_W;
    int jr  = tid - cq * OUT_W;
    float* ob = out + (size_t)roi * CHN * BINS + i * OUT_W + jr;
    #pragma unroll
    for (int k = 0; k < 4; ++k)
        ob[(size_t)(cq + 64 * k) * BINS] = s[tid + k * PTHREADS];
}

extern "C" void kernel_launch(void* const* d_in, const int* in_sizes, int n_in,
                              void* d_out, int out_size)
{
    const float* feat = (const float*)d_in[0];
    const float* rois = (const float*)d_in[1];
    float* out = (float*)d_out;

    dim3 tgrid((HW + 31) / 32, CHN / 32, N_IMG);
    dim3 tblock(32, 8);
    transpose_kernel<<<tgrid, tblock>>>(feat, rois);

    dim3 pgrid(NUM_ROIS, OUT_H);
    dim3 pblock(C4, OUT_W);
    roi_pool_bin<<<pgrid, pblock>>>(out);
}